// round 17
// baseline (speedup 1.0000x reference)
#include <cuda_runtime.h>
#include <cuda_fp16.h>
#include <stdint.h>

#define NN 100000
#define NE 800000

// ---------------- scratch (device globals; no allocation allowed) ----------------
__device__ __align__(16) int    g_deg[NN];
__device__ __align__(16) int    g_cursor[NN];
__device__ __align__(16) float  g_dinv[NN];
__device__ __align__(16) int    g_ptr[NN + 1];
__device__ __align__(16) int    g_src[NE];
__device__ __align__(16) float  g_w[NE];
__device__ __align__(16) float  g_bufA[(size_t)NN * 384];
__device__ __align__(16) float  g_bufB[(size_t)NN * 384];
__device__ __align__(16) __half g_tmpT[(size_t)NN * 256];   // fp16 intermediate
__device__ __align__(16) __half g_tmpQ[(size_t)NN * 128];   // fp16 intermediate
__device__ __align__(16) float  g_sc[384];
__device__ __align__(16) float  g_sh[384];
// A pre-transformed to fp16 (padded 128 rows so tail-CTA cp.async stays in-bounds)
__device__ __align__(16) __half g_Ah[(size_t)(NN + 128) * 384];
// weights pre-converted to fp16 AND transposed to [n][k] (k contiguous)
__device__ __align__(16) __half g_W0c[3 * 128 * 128];
__device__ __align__(16) __half g_W1c[3 * 128 * 384];
__device__ __align__(16) __half g_W2c[3 * 128 * 384];
__device__ double g_sums[768];
__device__ int g_bsum[128];
__device__ int g_boff[128];

// ---------------- graph preprocessing ----------------
__global__ void k_zero_setup() {
    int i = blockIdx.x * blockDim.x + threadIdx.x;
    if (i < NN) { g_deg[i] = 0; g_cursor[i] = 0; }
    if (i < 768) g_sums[i] = 0.0;
}
__global__ void k_hist(const int* __restrict__ col) {
    int i = blockIdx.x * blockDim.x + threadIdx.x;
    if (i < NE) atomicAdd(&g_deg[col[i]], 1);
}
__global__ void k_scan1() {
    __shared__ int sm[1024];
    int b = blockIdx.x, t = threadIdx.x;
    int i = b * 1024 + t;
    int v = (i < NN) ? g_deg[i] : 0;
    if (i < NN) g_dinv[i] = v > 0 ? rsqrtf((float)v) : 0.0f;
    sm[t] = v;
    __syncthreads();
    for (int off = 1; off < 1024; off <<= 1) {
        int add = (t >= off) ? sm[t - off] : 0;
        __syncthreads();
        sm[t] += add;
        __syncthreads();
    }
    if (i < NN) g_ptr[i] = sm[t] - v;
    if (t == 1023) g_bsum[b] = sm[1023];
}
__global__ void k_scan2() {
    __shared__ int sm[128];
    int t = threadIdx.x;
    const int nb = (NN + 1023) >> 10;
    int v = (t < nb) ? g_bsum[t] : 0;
    sm[t] = v;
    __syncthreads();
    for (int off = 1; off < 128; off <<= 1) {
        int add = (t >= off) ? sm[t - off] : 0;
        __syncthreads();
        sm[t] += add;
        __syncthreads();
    }
    if (t < nb) g_boff[t] = sm[t] - v;
    if (t == 0) g_ptr[NN] = NE;
}
__global__ void k_scan3() {
    int i = blockIdx.x * blockDim.x + threadIdx.x;
    if (i < NN) g_ptr[i] += g_boff[i >> 10];
}
__global__ void k_fill(const int* __restrict__ row, const int* __restrict__ col) {
    int i = blockIdx.x * blockDim.x + threadIdx.x;
    if (i >= NE) return;
    int r = row[i], c = col[i];
    int p = g_ptr[c] + atomicAdd(&g_cursor[c], 1);
    g_src[p] = r;
    g_w[p] = g_dinv[r] * g_dinv[c];
}

// convert+transpose weights -> [h][n][k] fp16; also convert x -> g_Ah (K=128)
#define W0N (3 * 128 * 128)
#define W12N (3 * 128 * 384)
#define XN (NN * 128)
__global__ void k_wcvt(const float* __restrict__ W0, const float* __restrict__ W1,
                       const float* __restrict__ W2, const float* __restrict__ x) {
    int i = blockIdx.x * blockDim.x + threadIdx.x;
    if (i < W0N) {
        int h = i / (128 * 128), r = i % (128 * 128);
        int n = r / 128, k = r % 128;
        g_W0c[i] = __float2half_rn(W0[h * 128 * 128 + k * 128 + n]);
    }
    if (i < W12N) {
        int h = i / (128 * 384), r = i % (128 * 384);
        int n = r / 384, k = r % 384;
        g_W1c[i] = __float2half_rn(W1[h * 384 * 128 + k * 128 + n]);
        g_W2c[i] = __float2half_rn(W2[h * 384 * 128 + k * 128 + n]);
    }
    if (i < XN) g_Ah[i] = __float2half_rn(x[i]);
}

// BN+ReLU+cvt transform: src [NN,384] fp32 -> g_Ah [NN,384] fp16
#define PREP4 (NN * 96)
__global__ void k_prep(const float* __restrict__ src) {
    int i = blockIdx.x * blockDim.x + threadIdx.x;
    if (i >= PREP4) return;
    int c = (i % 96) * 4;
    float4 v = reinterpret_cast<const float4*>(src)[i];
    float4 scv = *reinterpret_cast<const float4*>(g_sc + c);
    float4 shv = *reinterpret_cast<const float4*>(g_sh + c);
    __half2 h0 = __floats2half2_rn(fmaxf(fmaf(v.x, scv.x, shv.x), 0.f),
                                   fmaxf(fmaf(v.y, scv.y, shv.y), 0.f));
    __half2 h1 = __floats2half2_rn(fmaxf(fmaf(v.z, scv.z, shv.z), 0.f),
                                   fmaxf(fmaf(v.w, scv.w, shv.w), 0.f));
    __half2* dst = reinterpret_cast<__half2*>(g_Ah) + i * 2;
    dst[0] = h0;
    dst[1] = h1;
}

// ---------------- SPMM kernels: fp16 gathers, fp32 accumulate ----------------
__device__ __forceinline__ float4 h4_to_f4(uint2 p) {
    float2 lo = __half22float2(*reinterpret_cast<__half2*>(&p.x));
    float2 hi = __half22float2(*reinterpret_cast<__half2*>(&p.y));
    return make_float4(lo.x, lo.y, hi.x, hi.y);
}
__device__ __forceinline__ uint2 f4_to_h4(float4 v) {
    __half2 lo = __floats2half2_rn(v.x, v.y);
    __half2 hi = __floats2half2_rn(v.z, v.w);
    uint2 r;
    r.x = *reinterpret_cast<uint32_t*>(&lo);
    r.y = *reinterpret_cast<uint32_t*>(&hi);
    return r;
}

// T fp16 [NN,256]: cols [0,128) -> out1 (fp32 h cols 128:256, stats),
//                  cols [128,256) -> out2 (fp16 tmpQ)
__global__ void __launch_bounds__(256) k_spmm256(
    const __half* __restrict__ T,
    float* __restrict__ out1, int ld1,
    __half* __restrict__ out2, int do_stats)
{
    __shared__ float ssum[128], ssq[128];
    const int tid = threadIdx.x;
    if (tid < 128) { ssum[tid] = 0.f; ssq[tid] = 0.f; }
    __syncthreads();
    const int lane = tid & 31, wp = tid >> 5;
    const int base = blockIdx.x * 64 + wp * 8;
    float ls[4] = {0.f, 0.f, 0.f, 0.f};
    float lq[4] = {0.f, 0.f, 0.f, 0.f};
    for (int nn = 0; nn < 8; nn++) {
        int node = base + nn;
        if (node >= NN) break;
        int s = g_ptr[node], e = g_ptr[node + 1];
        float4 a1 = make_float4(0.f, 0.f, 0.f, 0.f);
        float4 a2 = make_float4(0.f, 0.f, 0.f, 0.f);
        for (int j = s; j < e; j++) {
            int u = __ldg(&g_src[j]);
            float w = __ldg(&g_w[j]);
            const uint2* rp = reinterpret_cast<const uint2*>(T + (size_t)u * 256);
            float4 v1 = h4_to_f4(__ldg(rp + lane));
            float4 v2 = h4_to_f4(__ldg(rp + 32 + lane));
            a1.x = fmaf(w, v1.x, a1.x); a1.y = fmaf(w, v1.y, a1.y);
            a1.z = fmaf(w, v1.z, a1.z); a1.w = fmaf(w, v1.w, a1.w);
            a2.x = fmaf(w, v2.x, a2.x); a2.y = fmaf(w, v2.y, a2.y);
            a2.z = fmaf(w, v2.z, a2.z); a2.w = fmaf(w, v2.w, a2.w);
        }
        reinterpret_cast<float4*>(out1 + (size_t)node * ld1)[lane] = a1;
        reinterpret_cast<uint2*>(out2 + (size_t)node * 128)[lane] = f4_to_h4(a2);
        if (do_stats) {
            ls[0] += a1.x; lq[0] = fmaf(a1.x, a1.x, lq[0]);
            ls[1] += a1.y; lq[1] = fmaf(a1.y, a1.y, lq[1]);
            ls[2] += a1.z; lq[2] = fmaf(a1.z, a1.z, lq[2]);
            ls[3] += a1.w; lq[3] = fmaf(a1.w, a1.w, lq[3]);
        }
    }
    if (do_stats) {
        int c = lane * 4;
#pragma unroll
        for (int k = 0; k < 4; k++) {
            atomicAdd(&ssum[c + k], ls[k]);
            atomicAdd(&ssq[c + k], lq[k]);
        }
        __syncthreads();
        if (tid < 128) {
            atomicAdd(&g_sums[128 + tid], (double)ssum[tid]);
            atomicAdd(&g_sums[512 + tid], (double)ssq[tid]);
        }
    }
}

// Q fp16 [NN,128] -> out fp32 (h cols 256:384, ld 384)
__global__ void __launch_bounds__(256) k_spmm2(
    const __half* __restrict__ Q, float* __restrict__ out, int do_stats)
{
    __shared__ float ssum[128], ssq[128];
    const int tid = threadIdx.x;
    if (tid < 128) { ssum[tid] = 0.f; ssq[tid] = 0.f; }
    __syncthreads();
    const int lane = tid & 31, wp = tid >> 5;
    const int base = blockIdx.x * 64 + wp * 8;
    float ls[4] = {0.f, 0.f, 0.f, 0.f};
    float lq[4] = {0.f, 0.f, 0.f, 0.f};
    for (int nn = 0; nn < 8; nn++) {
        int node = base + nn;
        if (node >= NN) break;
        int s = g_ptr[node], e = g_ptr[node + 1];
        float4 acc = make_float4(0.f, 0.f, 0.f, 0.f);
        for (int j = s; j < e; j++) {
            int u = __ldg(&g_src[j]);
            float w = __ldg(&g_w[j]);
            float4 v = h4_to_f4(__ldg(reinterpret_cast<const uint2*>(Q + (size_t)u * 128) + lane));
            acc.x = fmaf(w, v.x, acc.x);
            acc.y = fmaf(w, v.y, acc.y);
            acc.z = fmaf(w, v.z, acc.z);
            acc.w = fmaf(w, v.w, acc.w);
        }
        reinterpret_cast<float4*>(out + (size_t)node * 384)[lane] = acc;
        if (do_stats) {
            ls[0] += acc.x; lq[0] = fmaf(acc.x, acc.x, lq[0]);
            ls[1] += acc.y; lq[1] = fmaf(acc.y, acc.y, lq[1]);
            ls[2] += acc.z; lq[2] = fmaf(acc.z, acc.z, lq[2]);
            ls[3] += acc.w; lq[3] = fmaf(acc.w, acc.w, lq[3]);
        }
    }
    if (do_stats) {
        int c = lane * 4;
#pragma unroll
        for (int k = 0; k < 4; k++) {
            atomicAdd(&ssum[c + k], ls[k]);
            atomicAdd(&ssq[c + k], lq[k]);
        }
        __syncthreads();
        if (tid < 128) {
            atomicAdd(&g_sums[256 + tid], (double)ssum[tid]);
            atomicAdd(&g_sums[640 + tid], (double)ssq[tid]);
        }
    }
}

// ---------------- FP16 GEMM: m16n8k16, 4-stage cp.async, ldmatrix ----------------
__device__ __forceinline__ void mma_f16(float* d, const uint32_t* a, const uint32_t* b) {
    asm volatile(
        "mma.sync.aligned.m16n8k16.row.col.f32.f16.f16.f32 "
        "{%0,%1,%2,%3}, {%4,%5,%6,%7}, {%8,%9}, {%0,%1,%2,%3};\n"
        : "+f"(d[0]), "+f"(d[1]), "+f"(d[2]), "+f"(d[3])
        : "r"(a[0]), "r"(a[1]), "r"(a[2]), "r"(a[3]),
          "r"(b[0]), "r"(b[1]));
}
__device__ __forceinline__ uint32_t smem_u32(const void* p) {
    uint32_t a;
    asm("{ .reg .u64 t; cvta.to.shared.u64 t, %1; cvt.u32.u64 %0, t; }" : "=r"(a) : "l"(p));
    return a;
}
__device__ __forceinline__ void cp_async16(uint32_t dst, const void* src) {
    asm volatile("cp.async.cg.shared.global [%0], [%1], 16;" :: "r"(dst), "l"(src) : "memory");
}
#define CP_COMMIT() asm volatile("cp.async.commit_group;" ::: "memory")
#define CP_WAIT2()  asm volatile("cp.async.wait_group 2;" ::: "memory")
__device__ __forceinline__ void ldsm_x4(uint32_t& r0, uint32_t& r1, uint32_t& r2,
                                        uint32_t& r3, uint32_t addr) {
    asm volatile("ldmatrix.sync.aligned.m8n8.x4.shared.b16 {%0,%1,%2,%3}, [%4];"
                 : "=r"(r0), "=r"(r1), "=r"(r2), "=r"(r3) : "r"(addr));
}

#define PITCHB 80
#define BUF_BYTES (128 * PITCHB)
#define BOFF (4 * BUF_BYTES)
#define SSUM_OFF (8 * BUF_BYTES)
#define GEMM_SMEM (SSUM_OFF + 1024)

__device__ __forceinline__ void cp_chunk(
    const __half* __restrict__ src, int K, int kb, int tid, uint32_t dst)
{
#pragma unroll
    for (int j = 0; j < 2; j++) {
        int idx = tid + j * 256;
        int m = idx >> 2, kq = (idx & 3) * 8;
        cp_async16(dst + (uint32_t)(m * PITCHB + kq * 2),
                   src + (size_t)m * K + kb + kq);
    }
}

// gridDim = (ceil(M/128), 3). hop 0 -> fp32 Hout cols 0:128 (stats);
// hops 1/2 -> fp16 T cols 0:128 / 128:256.
__global__ void __launch_bounds__(256, 2) k_gemm3(
    const __half* __restrict__ Ah, int M, int K,
    const __half* __restrict__ Wcall, const float* __restrict__ ball,
    float* __restrict__ Hout, __half* __restrict__ T, int do_stats)
{
    extern __shared__ char dsm[];
    float* ssum = reinterpret_cast<float*>(dsm + SSUM_OFF);
    float* ssq = ssum + 128;

    const int tid = threadIdx.x;
    const int hop = blockIdx.y;
    const __half* Wc = Wcall + (size_t)hop * 128 * K;
    const float* bias = ball + hop * 128;
    const int stats = do_stats && (hop == 0);

    if (tid < 128) { ssum[tid] = 0.f; ssq[tid] = 0.f; }

    const int wid = tid >> 5, lane = tid & 31;
    const int g = lane >> 2, t = lane & 3;
    const int wm = (wid >> 1) * 32, wn = (wid & 1) * 64;
    const int row0 = blockIdx.x * 128;
    const uint32_t sb = smem_u32(dsm);

    const __half* Arow = Ah + (size_t)row0 * K;

    const int l16 = lane & 15;
    const int khalf = (lane >> 4) * 8;
    uint32_t aaddr[2];
#pragma unroll
    for (int im = 0; im < 2; im++)
        aaddr[im] = sb + (uint32_t)((wm + im * 16 + l16) * PITCHB + khalf * 2);
    uint32_t baddr[4];
#pragma unroll
    for (int in2 = 0; in2 < 4; in2++)
        baddr[in2] = sb + BOFF + (uint32_t)((wn + in2 * 16 + l16) * PITCHB + khalf * 2);

    float acc[2][8][4];
#pragma unroll
    for (int im = 0; im < 2; im++)
#pragma unroll
        for (int in = 0; in < 8; in++)
#pragma unroll
            for (int q = 0; q < 4; q++) acc[im][in][q] = 0.f;

    const int NT = K >> 5;

#pragma unroll
    for (int s = 0; s < 3; s++) {
        cp_chunk(Arow, K, s * 32, tid, sb + s * BUF_BYTES);
        cp_chunk(Wc, K, s * 32, tid, sb + BOFF + s * BUF_BYTES);
        CP_COMMIT();
    }

    for (int kt = 0; kt < NT; kt++) {
        CP_WAIT2();
        __syncthreads();
        const int ps = kt + 3;
        if (ps < NT) {
            const uint32_t st = (uint32_t)(ps & 3) * BUF_BYTES;
            cp_chunk(Arow, K, ps * 32, tid, sb + st);
            cp_chunk(Wc, K, ps * 32, tid, sb + BOFF + st);
        }
        CP_COMMIT();

        const uint32_t soff = (uint32_t)(kt & 3) * BUF_BYTES;
#pragma unroll
        for (int ks2 = 0; ks2 < 2; ks2++) {
            const uint32_t koff = soff + ks2 * 32;
            uint32_t af[2][4], bf[8][2];
            ldsm_x4(af[0][0], af[0][1], af[0][2], af[0][3], aaddr[0] + koff);
            ldsm_x4(af[1][0], af[1][1], af[1][2], af[1][3], aaddr[1] + koff);
#pragma unroll
            for (int in2 = 0; in2 < 4; in2++) {
                uint32_t r0, r1, r2, r3;
                ldsm_x4(r0, r1, r2, r3, baddr[in2] + koff);
                bf[2 * in2][0] = r0;
                bf[2 * in2 + 1][0] = r1;
                bf[2 * in2][1] = r2;
                bf[2 * in2 + 1][1] = r3;
            }
#pragma unroll
            for (int im = 0; im < 2; im++)
#pragma unroll
                for (int in = 0; in < 8; in++)
                    mma_f16(acc[im][in], af[im], bf[in]);
        }
    }

    // epilogue: bias + store (hop0 -> fp32 Hout, hops 1/2 -> fp16 T)
#pragma unroll
    for (int im = 0; im < 2; im++) {
        int r0 = row0 + wm + im * 16 + g;
#pragma unroll
        for (int in = 0; in < 8; in++) {
            int c0 = wn + in * 8 + 2 * t;
            float b0 = __ldg(&bias[c0]), b1 = __ldg(&bias[c0 + 1]);
            if (hop == 0) {
                if (r0 < M) {
                    float2 v = make_float2(acc[im][in][0] + b0, acc[im][in][1] + b1);
                    *reinterpret_cast<float2*>(Hout + (size_t)r0 * 384 + c0) = v;
                }
                if (r0 + 8 < M) {
                    float2 v = make_float2(acc[im][in][2] + b0, acc[im][in][3] + b1);
                    *reinterpret_cast<float2*>(Hout + (size_t)(r0 + 8) * 384 + c0) = v;
                }
            } else {
                int tc = (hop - 1) * 128 + c0;
                if (r0 < M) {
                    __half2 v = __floats2half2_rn(acc[im][in][0] + b0, acc[im][in][1] + b1);
                    *reinterpret_cast<__half2*>(T + (size_t)r0 * 256 + tc) = v;
                }
                if (r0 + 8 < M) {
                    __half2 v = __floats2half2_rn(acc[im][in][2] + b0, acc[im][in][3] + b1);
                    *reinterpret_cast<__half2*>(T + (size_t)(r0 + 8) * 256 + tc) = v;
                }
            }
        }
    }

    if (stats) {
        __syncthreads();
#pragma unroll
        for (int in = 0; in < 8; in++) {
            int c0 = wn + in * 8 + 2 * t;
            float b0 = __ldg(&bias[c0]), b1 = __ldg(&bias[c0 + 1]);
            float s0 = 0.f, s1 = 0.f, q0 = 0.f, q1 = 0.f;
#pragma unroll
            for (int im = 0; im < 2; im++) {
                int r0 = row0 + wm + im * 16 + g;
                if (r0 < M) {
                    float v0 = acc[im][in][0] + b0, v1 = acc[im][in][1] + b1;
                    s0 += v0; q0 = fmaf(v0, v0, q0);
                    s1 += v1; q1 = fmaf(v1, v1, q1);
                }
                if (r0 + 8 < M) {
                    float v0 = acc[im][in][2] + b0, v1 = acc[im][in][3] + b1;
                    s0 += v0; q0 = fmaf(v0, v0, q0);
                    s1 += v1; q1 = fmaf(v1, v1, q1);
                }
            }
            atomicAdd(&ssum[c0], s0);
            atomicAdd(&ssq[c0], q0);
            atomicAdd(&ssum[c0 + 1], s1);
            atomicAdd(&ssq[c0 + 1], q1);
        }
        __syncthreads();
        if (tid < 128) {
            atomicAdd(&g_sums[tid], (double)ssum[tid]);
            atomicAdd(&g_sums[384 + tid], (double)ssq[tid]);
        }
    }
}

// ---------------- BN coefficients (self-resetting sums) ----------------
__global__ void k_bncoef(const float* __restrict__ gamma, const float* __restrict__ beta) {
    int c = threadIdx.x;  // 384
    double inv_n = 1.0 / (double)NN;
    double mu = g_sums[c] * inv_n;
    double var = g_sums[384 + c] * inv_n - mu * mu;
    float inv = rsqrtf(fmaxf((float)var, 0.f) + 1e-5f);
    float gg = gamma[c];
    g_sc[c] = inv * gg;
    g_sh[c] = beta[c] - (float)mu * inv * gg;
    g_sums[c] = 0.0;
    g_sums[384 + c] = 0.0;
}

// ---------------- host orchestration ----------------
extern "C" void kernel_launch(void* const* d_in, const int* in_sizes, int n_in,
                              void* d_out, int out_size) {
    const float* x  = (const float*)d_in[0];
    const int*   ei = (const int*)d_in[1];
    const float* W0 = (const float*)d_in[2];
    const float* b0 = (const float*)d_in[3];
    const float* W1 = (const float*)d_in[4];
    const float* b1 = (const float*)d_in[5];
    const float* W2 = (const float*)d_in[6];
    const float* b2 = (const float*)d_in[7];
    const float* gm = (const float*)d_in[8];
    const float* bt = (const float*)d_in[9];
    float* out = (float*)d_out;

    cudaFuncSetAttribute(k_gemm3, cudaFuncAttributeMaxDynamicSharedMemorySize, GEMM_SMEM);

    float *bufA, *bufB;
    __half *W0c, *W1c, *W2c, *Ah, *T, *tmpQ;
    cudaGetSymbolAddress((void**)&bufA, g_bufA);
    cudaGetSymbolAddress((void**)&bufB, g_bufB);
    cudaGetSymbolAddress((void**)&T, g_tmpT);
    cudaGetSymbolAddress((void**)&tmpQ, g_tmpQ);
    cudaGetSymbolAddress((void**)&W0c, g_W0c);
    cudaGetSymbolAddress((void**)&W1c, g_W1c);
    cudaGetSymbolAddress((void**)&W2c, g_W2c);
    cudaGetSymbolAddress((void**)&Ah, g_Ah);

    const int* row = ei;
    const int* col = ei + NE;

    const dim3 gg((NN + 127) / 128, 3);
    const int sg = (NN + 63) / 64;

    // launches 1-3: prep independent of graph structure
    k_zero_setup<<<(NN + 255) / 256, 256>>>();
    k_hist<<<(NE + 255) / 256, 256>>>(col);
    k_wcvt<<<(XN + 255) / 256, 256>>>(W0, W1, W2, x);
    // launch 4: layer-0 GEMM — profiled slot
    k_gemm3<<<gg, 256, GEMM_SMEM>>>(Ah, NN, 128, W0c, b0, bufA, T, 1);
    // finish graph prep
    k_scan1<<<(NN + 1023) / 1024, 1024>>>();
    k_scan2<<<1, 128>>>();
    k_scan3<<<(NN + 255) / 256, 256>>>();
    k_fill<<<(NE + 255) / 256, 256>>>(row, col);
    // layer 0 SPMM + BN coefficients
    k_spmm256<<<sg, 256>>>(T, bufA + 128, 384, tmpQ, 1);
    k_spmm2<<<sg, 256>>>(tmpQ, bufA + 256, 1);
    k_bncoef<<<1, 384>>>(gm, bt);

    // layer 1
    k_prep<<<(PREP4 + 255) / 256, 256>>>(bufA);
    k_gemm3<<<gg, 256, GEMM_SMEM>>>(Ah, NN, 384, W1c, b1, bufB, T, 1);
    k_spmm256<<<sg, 256>>>(T, bufB + 128, 384, tmpQ, 1);
    k_spmm2<<<sg, 256>>>(tmpQ, bufB + 256, 1);
    k_bncoef<<<1, 384>>>(gm + 384, bt + 384);

    // layer 2
    k_prep<<<(PREP4 + 255) / 256, 256>>>(bufB);
    k_gemm3<<<gg, 256, GEMM_SMEM>>>(Ah, NN, 384, W2c, b2, out, T, 0);
    k_spmm256<<<sg, 256>>>(T, out + 128, 384, tmpQ, 0);
    k_spmm2<<<sg, 256>>>(tmpQ, out + 256, 0);
}